// round 6
// baseline (speedup 1.0000x reference)
#include <cuda_runtime.h>
#include <cuda_fp16.h>
#include <cstdint>

// ---------------------------------------------------------------------------
// FullAttention  out = softmax(Q K^T / 8) V ; outputs tuple (output, attn)
// B=8 H=8 S=1024 D=64 fp32.
// compute_103 baseline PTX only (no tcgen05 on this toolchain target):
// mma.sync.aligned.m16n8k16 fp16 (HMMA) + ldmatrix, fp16-split QK for accuracy.
//
// CTA = 128 q rows x one (b,h); 256 threads / 8 warps.
// warp (rg=w>>1, nh=w&1): rows [32rg,32rg+32), keys [64nh,64nh+64) per 128-key
// block. Pass 1: online row max m and sum l (per nh-half, merged via smem).
// Pass 2: recompute S (bit-identical), p = exp(s-m)/l, stream attn to gmem,
// feed p straight into PV mma via the C->A fragment identity (no smem P).
// ---------------------------------------------------------------------------

namespace {
constexpr int Sn = 1024, Dn = 64, BH = 64, QB = 128, KBLK = 128, NJ = 8;
constexpr int STR = 72;                       // halves per smem tile row (144B: LDSM conflict-free)
constexpr int SM_QH  = 0;                     // 128x72 half = 18432 B each
constexpr int SM_QL  = 18432;
constexpr int SM_KH  = 36864;
constexpr int SM_KL  = 55296;
constexpr int SM_V   = 73728;
constexpr int SM_RED = 92160;                 // 128 rows x 2 halves x float2 = 2048 B
constexpr int SMEM_SZ = 94208;
constexpr int OB_STR = 68;                    // epilogue O buffer stride (floats), overlays SM_KH
} // namespace

static __device__ __forceinline__ uint32_t smem_u32(const void* p) {
    uint32_t a;
    asm("{ .reg .u64 t; cvta.to.shared.u64 t, %1; cvt.u32.u64 %0, t; }"
        : "=r"(a) : "l"(p));
    return a;
}

#define LDSM_X4(R, a)                                                          \
    asm volatile("ldmatrix.sync.aligned.m8n8.x4.shared.b16 {%0,%1,%2,%3}, [%4];" \
                 : "=r"((R)[0]), "=r"((R)[1]), "=r"((R)[2]), "=r"((R)[3])      \
                 : "r"(a))

#define LDSM_X4T(R, a)                                                         \
    asm volatile("ldmatrix.sync.aligned.m8n8.x4.trans.shared.b16 {%0,%1,%2,%3}, [%4];" \
                 : "=r"((R)[0]), "=r"((R)[1]), "=r"((R)[2]), "=r"((R)[3])      \
                 : "r"(a))

#define MMA(C, A, b0, b1)                                                      \
    asm volatile(                                                              \
        "mma.sync.aligned.m16n8k16.row.col.f32.f16.f16.f32 "                   \
        "{%0,%1,%2,%3}, {%4,%5,%6,%7}, {%8,%9}, {%0,%1,%2,%3};"                \
        : "+f"((C)[0]), "+f"((C)[1]), "+f"((C)[2]), "+f"((C)[3])               \
        : "r"((A)[0]), "r"((A)[1]), "r"((A)[2]), "r"((A)[3]), "r"(b0), "r"(b1))

static __device__ __forceinline__ uint32_t h2u(float a, float b) {
    __half2 h = __floats2half2_rn(a, b);
    return *reinterpret_cast<uint32_t*>(&h);
}

// convert a 128x64 fp32 tile -> (hi, lo) fp16 split tiles in smem
static __device__ __forceinline__ void fill_split(char* smem, int offH, int offL,
                                                  const float* __restrict__ g,
                                                  float scale, int tid) {
    const float4* src = (const float4*)g;
    #pragma unroll
    for (int it = 0; it < 8; ++it) {
        int i = tid + it * 256;
        float4 v = src[i];
        v.x *= scale; v.y *= scale; v.z *= scale; v.w *= scale;
        int r = i >> 4, c = (i & 15) << 2;
        __half h0 = __float2half_rn(v.x), h1 = __float2half_rn(v.y);
        __half h2_ = __float2half_rn(v.z), h3 = __float2half_rn(v.w);
        __half e0 = __float2half_rn(v.x - __half2float(h0));
        __half e1 = __float2half_rn(v.y - __half2float(h1));
        __half e2 = __float2half_rn(v.z - __half2float(h2_));
        __half e3 = __float2half_rn(v.w - __half2float(h3));
        __half2* dH = (__half2*)(smem + offH + (r * STR + c) * 2);
        dH[0] = __halves2half2(h0, h1);
        dH[1] = __halves2half2(h2_, h3);
        __half2* dL = (__half2*)(smem + offL + (r * STR + c) * 2);
        dL[0] = __halves2half2(e0, e1);
        dL[1] = __halves2half2(e2, e3);
    }
}

// convert a 128x64 fp32 tile -> fp16 tile in smem
static __device__ __forceinline__ void fill_h(char* smem, int off,
                                              const float* __restrict__ g, int tid) {
    const float4* src = (const float4*)g;
    #pragma unroll
    for (int it = 0; it < 8; ++it) {
        int i = tid + it * 256;
        float4 v = src[i];
        int r = i >> 4, c = (i & 15) << 2;
        __half2* d = (__half2*)(smem + off + (r * STR + c) * 2);
        d[0] = __floats2half2_rn(v.x, v.y);
        d[1] = __floats2half2_rn(v.z, v.w);
    }
}

// S[2][8][4] = Q_tile(32 rows) @ K_tile^T (64 keys = this warp's nh half),
// fp16 split: qh*kh + qh*kl + ql*kh   (fp32 accumulate)
static __device__ __forceinline__ void compute_S(float S[2][8][4], uint32_t sb,
                                                 int rg, int nh, int lane) {
    #pragma unroll
    for (int mt = 0; mt < 2; ++mt)
        #pragma unroll
        for (int nt = 0; nt < 8; ++nt)
            #pragma unroll
            for (int c = 0; c < 4; ++c) S[mt][nt][c] = 0.0f;

    const int aRow = lane & 15;
    const int aCol = 8 * (lane >> 4);
    const int bRow = (lane & 7) + 8 * (lane >> 4);
    const int bCol = 8 * ((lane >> 3) & 1);

    #pragma unroll 1
    for (int ks = 0; ks < 4; ++ks) {
        const int k0 = 16 * ks;
        uint32_t aH[2][4], aL[2][4];
        #pragma unroll
        for (int mt = 0; mt < 2; ++mt) {
            uint32_t ad = sb + SM_QH +
                (uint32_t)(((32 * rg + 16 * mt + aRow) * STR + k0 + aCol) * 2);
            LDSM_X4(aH[mt], ad);
            LDSM_X4(aL[mt], ad + (SM_QL - SM_QH));
        }
        #pragma unroll
        for (int np = 0; np < 4; ++np) {
            const int n0 = 64 * nh + 16 * np;
            uint32_t bd = sb + SM_KH +
                (uint32_t)(((n0 + bRow) * STR + k0 + bCol) * 2);
            uint32_t bHf[4], bLf[4];
            LDSM_X4(bHf, bd);
            LDSM_X4(bLf, bd + (SM_KL - SM_KH));
            #pragma unroll
            for (int mt = 0; mt < 2; ++mt) {
                MMA(S[mt][2 * np],     aH[mt], bHf[0], bHf[1]);
                MMA(S[mt][2 * np],     aL[mt], bHf[0], bHf[1]);
                MMA(S[mt][2 * np],     aH[mt], bLf[0], bLf[1]);
                MMA(S[mt][2 * np + 1], aH[mt], bHf[2], bHf[3]);
                MMA(S[mt][2 * np + 1], aL[mt], bHf[2], bHf[3]);
                MMA(S[mt][2 * np + 1], aH[mt], bLf[2], bLf[3]);
            }
        }
    }
}

__global__ void __launch_bounds__(256, 1)
fa_kernel(const float* __restrict__ gQ, const float* __restrict__ gK,
          const float* __restrict__ gV, float* __restrict__ gO,
          float* __restrict__ gA) {
    extern __shared__ char smem[];
    const uint32_t sb = smem_u32(smem);
    const int tid = threadIdx.x;
    const int lane = tid & 31;
    const int w = tid >> 5;
    const int rg = w >> 1;     // row group: rows [32rg, 32rg+32)
    const int nh = w & 1;      // key half within 128-key block
    const int qb = blockIdx.x; // 0..7
    const int bh = blockIdx.y; // 0..63

    const float* Qg = gQ + ((size_t)bh * Sn + (size_t)qb * QB) * Dn;
    const float* Kg = gK + (size_t)bh * Sn * Dn;
    const float* Vg = gV + (size_t)bh * Sn * Dn;
    float* Og = gO + ((size_t)bh * Sn + (size_t)qb * QB) * Dn;
    float* Ag = gA + ((size_t)bh * Sn + (size_t)qb * QB) * (size_t)Sn;

    // Q tile, pre-scaled by 1/sqrt(D), fp16-split
    fill_split(smem, SM_QH, SM_QL, Qg, 0.125f, tid);

    const float NEGINF = __int_as_float(0xff800000);
    float m[4], l[4];
    #pragma unroll
    for (int i = 0; i < 4; ++i) { m[i] = NEGINF; l[i] = 0.0f; }

    // ===================== pass 1: row max + sum-exp =====================
    #pragma unroll 1
    for (int j = 0; j < NJ; ++j) {
        __syncthreads();
        fill_split(smem, SM_KH, SM_KL, Kg + (size_t)j * KBLK * Dn, 1.0f, tid);
        __syncthreads();
        float S[2][8][4];
        compute_S(S, sb, rg, nh, lane);
        #pragma unroll
        for (int mt = 0; mt < 2; ++mt)
            #pragma unroll
            for (int h = 0; h < 2; ++h) {
                const int idx = 2 * mt + h;
                float bm = NEGINF;
                #pragma unroll
                for (int nt = 0; nt < 8; ++nt)
                    bm = fmaxf(bm, fmaxf(S[mt][nt][2 * h], S[mt][nt][2 * h + 1]));
                bm = fmaxf(bm, __shfl_xor_sync(~0u, bm, 1));
                bm = fmaxf(bm, __shfl_xor_sync(~0u, bm, 2));
                const float nm = fmaxf(m[idx], bm);
                float s = 0.0f;
                #pragma unroll
                for (int nt = 0; nt < 8; ++nt)
                    s += __expf(S[mt][nt][2 * h] - nm) +
                         __expf(S[mt][nt][2 * h + 1] - nm);
                s += __shfl_xor_sync(~0u, s, 1);
                s += __shfl_xor_sync(~0u, s, 2);
                l[idx] = l[idx] * __expf(m[idx] - nm) + s;
                m[idx] = nm;
            }
    }

    // merge the two nh halves per row
    __syncthreads();
    float2* red = (float2*)(smem + SM_RED);
    if ((lane & 3) == 0) {
        #pragma unroll
        for (int mt = 0; mt < 2; ++mt)
            #pragma unroll
            for (int h = 0; h < 2; ++h) {
                const int row = 32 * rg + 16 * mt + (lane >> 2) + 8 * h;
                red[row * 2 + nh] = make_float2(m[2 * mt + h], l[2 * mt + h]);
            }
    }
    __syncthreads();
    float linv[4];
    #pragma unroll
    for (int mt = 0; mt < 2; ++mt)
        #pragma unroll
        for (int h = 0; h < 2; ++h) {
            const int row = 32 * rg + 16 * mt + (lane >> 2) + 8 * h;
            const float2 a = red[row * 2 + 0];
            const float2 b = red[row * 2 + 1];
            const float mf = fmaxf(a.x, b.x);
            const float lf = a.y * __expf(a.x - mf) + b.y * __expf(b.x - mf);
            m[2 * mt + h] = mf;
            linv[2 * mt + h] = 1.0f / lf;
        }

    // ============ pass 2: recompute, write attn, accumulate O ============
    float O[2][8][4];
    #pragma unroll
    for (int mt = 0; mt < 2; ++mt)
        #pragma unroll
        for (int dt = 0; dt < 8; ++dt)
            #pragma unroll
            for (int c = 0; c < 4; ++c) O[mt][dt][c] = 0.0f;

    const int vRow = (lane & 7) + 8 * ((lane >> 3) & 1);
    const int vCol = 8 * (lane >> 4);

    #pragma unroll 1
    for (int j = 0; j < NJ; ++j) {
        __syncthreads();
        fill_split(smem, SM_KH, SM_KL, Kg + (size_t)j * KBLK * Dn, 1.0f, tid);
        fill_h(smem, SM_V, Vg + (size_t)j * KBLK * Dn, tid);
        __syncthreads();
        float S[2][8][4];
        compute_S(S, sb, rg, nh, lane);   // identical to pass 1 -> same s bits

        uint32_t aP[2][4][4];
        #pragma unroll
        for (int mt = 0; mt < 2; ++mt) {
            const int r0 = 32 * rg + 16 * mt + (lane >> 2);
            #pragma unroll
            for (int t = 0; t < 8; ++t) {
                const float p0 = __expf(S[mt][t][0] - m[2 * mt]) * linv[2 * mt];
                const float p1 = __expf(S[mt][t][1] - m[2 * mt]) * linv[2 * mt];
                const float p2 = __expf(S[mt][t][2] - m[2 * mt + 1]) * linv[2 * mt + 1];
                const float p3 = __expf(S[mt][t][3] - m[2 * mt + 1]) * linv[2 * mt + 1];
                const int col = j * 128 + nh * 64 + t * 8 + 2 * (lane & 3);
                __stcs((float2*)(Ag + (size_t)r0 * Sn + col), make_float2(p0, p1));
                __stcs((float2*)(Ag + (size_t)(r0 + 8) * Sn + col), make_float2(p2, p3));
                aP[mt][t >> 1][(t & 1) * 2 + 0] = h2u(p0, p1);
                aP[mt][t >> 1][(t & 1) * 2 + 1] = h2u(p2, p3);
            }
        }
        // O += P @ V   (P in regs via C->A fragment identity, V fp16 in smem)
        #pragma unroll
        for (int kc = 0; kc < 4; ++kc) {
            const int k0 = 64 * nh + 16 * kc;
            #pragma unroll
            for (int dp = 0; dp < 4; ++dp) {
                uint32_t vd = sb + SM_V +
                    (uint32_t)(((k0 + vRow) * STR + dp * 16 + vCol) * 2);
                uint32_t bV[4];
                LDSM_X4T(bV, vd);
                #pragma unroll
                for (int mt = 0; mt < 2; ++mt) {
                    MMA(O[mt][2 * dp],     aP[mt][kc], bV[0], bV[1]);
                    MMA(O[mt][2 * dp + 1], aP[mt][kc], bV[2], bV[3]);
                }
            }
        }
    }

    // ============ epilogue: merge nh partial O, write to gmem ============
    __syncthreads();
    float* Ob = (float*)(smem + SM_KH);   // 128 x 68 fp32, overlays K tiles
    if (nh == 0) {
        #pragma unroll
        for (int mt = 0; mt < 2; ++mt) {
            const int r0 = 32 * rg + 16 * mt + (lane >> 2);
            #pragma unroll
            for (int dt = 0; dt < 8; ++dt) {
                const int c = dt * 8 + 2 * (lane & 3);
                *(float2*)&Ob[r0 * OB_STR + c] = make_float2(O[mt][dt][0], O[mt][dt][1]);
                *(float2*)&Ob[(r0 + 8) * OB_STR + c] = make_float2(O[mt][dt][2], O[mt][dt][3]);
            }
        }
    }
    __syncthreads();
    if (nh == 1) {
        #pragma unroll
        for (int mt = 0; mt < 2; ++mt) {
            const int r0 = 32 * rg + 16 * mt + (lane >> 2);
            #pragma unroll
            for (int dt = 0; dt < 8; ++dt) {
                const int c = dt * 8 + 2 * (lane & 3);
                float2 u = *(float2*)&Ob[r0 * OB_STR + c];
                u.x += O[mt][dt][0]; u.y += O[mt][dt][1];
                *(float2*)&Ob[r0 * OB_STR + c] = u;
                float2 v = *(float2*)&Ob[(r0 + 8) * OB_STR + c];
                v.x += O[mt][dt][2]; v.y += O[mt][dt][3];
                *(float2*)&Ob[(r0 + 8) * OB_STR + c] = v;
            }
        }
    }
    __syncthreads();
    #pragma unroll
    for (int it = 0; it < 8; ++it) {
        const int i = tid + it * 256;
        const int r = i >> 4, c = (i & 15) << 2;
        float4 v = *(float4*)&Ob[r * OB_STR + c];
        ((float4*)Og)[i] = v;
    }
}

extern "C" void kernel_launch(void* const* d_in, const int* in_sizes, int n_in,
                              void* d_out, int out_size) {
    (void)in_sizes; (void)n_in; (void)out_size;
    const float* Q = (const float*)d_in[0];
    const float* K = (const float*)d_in[1];
    const float* V = (const float*)d_in[2];
    float* Out  = (float*)d_out;
    float* Attn = Out + (size_t)BH * Sn * Dn;   // tuple order: (output, attn)

    cudaFuncSetAttribute(fa_kernel,
                         cudaFuncAttributeMaxDynamicSharedMemorySize, SMEM_SZ);

    dim3 grid(Sn / QB, BH);   // (8, 64) = 512 CTAs
    fa_kernel<<<grid, 256, SMEM_SZ>>>(Q, K, V, Out, Attn);
}